// round 6
// baseline (speedup 1.0000x reference)
#include <cuda_runtime.h>
#include <cuda_bf16.h>

#define S_LEN 512
#define B_DIM 256
#define Z_DIM 64

// ---- packed f32x2 helpers (full fp32 precision, 2 MACs per instruction) ----
__device__ __forceinline__ unsigned long long pack2(float lo, float hi) {
    unsigned long long r;
    asm("mov.b64 %0, {%1, %2};" : "=l"(r) : "f"(lo), "f"(hi));
    return r;
}
__device__ __forceinline__ unsigned long long fma2(unsigned long long a,
                                                   unsigned long long b,
                                                   unsigned long long c) {
    unsigned long long d;
    asm("fma.rn.f32x2 %0, %1, %2, %3;" : "=l"(d) : "l"(a), "l"(b), "l"(c));
    return d;
}
__device__ __forceinline__ unsigned long long add2(unsigned long long a,
                                                   unsigned long long b) {
    unsigned long long d;
    asm("add.rn.f32x2 %0, %1, %2;" : "=l"(d) : "l"(a), "l"(b));
    return d;
}
__device__ __forceinline__ float hsum2(unsigned long long v) {
    float lo, hi;
    asm("mov.b64 {%0, %1}, %2;" : "=f"(lo), "=f"(hi) : "l"(v));
    return lo + hi;
}

// ---------------------------------------------------------------------------
// One WARP per (batch, direction). 512 CTAs x 32 threads.
//   blocks [0,256):   alpha[t] = e[t] * (alpha[t-1] @ T^T)   lane l: rows l, l+32
//   blocks [256,512): beta[t]  = (e[t+1]*beta[t+1]) @ T      lane l: cols l, l+32
// Recurrent 64-vector via double-buffered smem; ONE __syncwarp per step.
// Time loop unrolled x2 -> all buffer / prefetch names static (no local mem).
// ---------------------------------------------------------------------------
__global__ __launch_bounds__(32)
void hmm_fb_kernel(const int* __restrict__ inp,      // [S, B]
                   const float* __restrict__ T,      // [Z, Z]
                   const float* __restrict__ pi,     // [Z]
                   const float* __restrict__ emit,   // [X, Z]
                   float* __restrict__ alpha,        // [S, B, Z]
                   float* __restrict__ beta)         // [S, B, Z]
{
    const bool bwd = blockIdx.x >= B_DIM;
    const int  b   = blockIdx.x & (B_DIM - 1);
    const int  l   = threadIdx.x;          // lane
    const int  z0  = l;
    const int  z1  = l + 32;

    __shared__ __align__(16) float v_sh[2][Z_DIM];
    __shared__ int x_sh[S_LEN];

    #pragma unroll
    for (int t = l; t < S_LEN; t += 32) x_sh[t] = inp[t * B_DIM + b];

    // T pairs for both owned states.
    // fwd: row z pairs {T[z][2k],T[z][2k+1]};  bwd: col z pairs {T[2k][z],T[2k+1][z]}
    unsigned long long TpLo[Z_DIM / 2], TpHi[Z_DIM / 2];
    if (!bwd) {
        #pragma unroll
        for (int k = 0; k < Z_DIM; k += 4) {
            float4 a = *reinterpret_cast<const float4*>(&T[z0 * Z_DIM + k]);
            float4 c = *reinterpret_cast<const float4*>(&T[z1 * Z_DIM + k]);
            TpLo[k/2]   = pack2(a.x, a.y);  TpLo[k/2+1] = pack2(a.z, a.w);
            TpHi[k/2]   = pack2(c.x, c.y);  TpHi[k/2+1] = pack2(c.z, c.w);
        }
    } else {
        #pragma unroll
        for (int k = 0; k < Z_DIM; k += 2) {
            TpLo[k/2] = pack2(T[k * Z_DIM + z0], T[(k+1) * Z_DIM + z0]);
            TpHi[k/2] = pack2(T[k * Z_DIM + z1], T[(k+1) * Z_DIM + z1]);
        }
    }

    // dot of the 64-vector in VR against both T-pair sets -> (d0, d1)
#define DOT2(VR, d0, d1)                                                       \
    {                                                                          \
        const ulonglong2* p2 = reinterpret_cast<const ulonglong2*>(VR);        \
        unsigned long long s0=0,s1=0,s2=0,s3=0, r0=0,r1=0,r2=0,r3=0;           \
        _Pragma("unroll")                                                      \
        for (int q = 0; q < 16; q++) {                                         \
            ulonglong2 u = p2[q];                                              \
            if ((q & 1) == 0) {                                                \
                s0 = fma2(u.x, TpLo[2*q],   s0);                               \
                s1 = fma2(u.y, TpLo[2*q+1], s1);                               \
                r0 = fma2(u.x, TpHi[2*q],   r0);                               \
                r1 = fma2(u.y, TpHi[2*q+1], r1);                               \
            } else {                                                           \
                s2 = fma2(u.x, TpLo[2*q],   s2);                               \
                s3 = fma2(u.y, TpLo[2*q+1], s3);                               \
                r2 = fma2(u.x, TpHi[2*q],   r2);                               \
                r3 = fma2(u.y, TpHi[2*q+1], r3);                               \
            }                                                                  \
        }                                                                      \
        d0 = hsum2(add2(add2(s0, s2), add2(s1, s3)));                          \
        d1 = hsum2(add2(add2(r0, r2), add2(r1, r3)));                          \
    }

    if (!bwd) {
        float* aw = alpha + (size_t)b * Z_DIM;   // + t*B*Z per step
        // t = 0
        float e0 = emit[x_sh[0] * Z_DIM + z0], e1 = emit[x_sh[0] * Z_DIM + z1];
        float a0 = e0 * pi[z0], a1 = e1 * pi[z1];
        aw[z0] = a0; aw[z1] = a1;
        v_sh[0][z0] = a0; v_sh[0][z1] = a1;
        // prefetch e[1] (odd steps), e[2] (even steps)
        float eo0 = emit[x_sh[1] * Z_DIM + z0], eo1 = emit[x_sh[1] * Z_DIM + z1];
        float ee0 = emit[x_sh[2] * Z_DIM + z0], ee1 = emit[x_sh[2] * Z_DIM + z1];
        __syncwarp();

#define FWD_STEP(t, VR, VW, E0, E1)                                            \
    {                                                                          \
        int xp = x_sh[((t) + 2 < S_LEN) ? (t) + 2 : S_LEN - 1] * Z_DIM;        \
        float d0, d1; DOT2(VR, d0, d1);                                        \
        float n0 = (E0) * d0, n1 = (E1) * d1;                                  \
        E0 = emit[xp + z0]; E1 = emit[xp + z1];                                \
        float* ap = aw + (size_t)(t) * B_DIM * Z_DIM;                          \
        ap[z0] = n0; ap[z1] = n1;                                              \
        (VW)[z0] = n0; (VW)[z1] = n1;                                          \
        __syncwarp();                                                          \
    }

        for (int t = 1; t < S_LEN - 1; t += 2) {
            FWD_STEP(t,     v_sh[0], v_sh[1], eo0, eo1);
            FWD_STEP(t + 1, v_sh[1], v_sh[0], ee0, ee1);
        }
        FWD_STEP(S_LEN - 1, v_sh[0], v_sh[1], eo0, eo1);
#undef FWD_STEP
    } else {
        float* bw = beta + (size_t)b * Z_DIM;
        // t = S-1: beta = 1, c[S-1] = e[S-1]
        {
            float* bp = bw + (size_t)(S_LEN - 1) * B_DIM * Z_DIM;
            bp[z0] = 1.0f; bp[z1] = 1.0f;
            int xi = x_sh[S_LEN - 1] * Z_DIM;
            v_sh[1][z0] = emit[xi + z0];
            v_sh[1][z1] = emit[xi + z1];
        }
        // prefetch e[510] (even steps), e[509] (odd steps)
        float ee0 = emit[x_sh[S_LEN - 2] * Z_DIM + z0], ee1 = emit[x_sh[S_LEN - 2] * Z_DIM + z1];
        float eo0 = emit[x_sh[S_LEN - 3] * Z_DIM + z0], eo1 = emit[x_sh[S_LEN - 3] * Z_DIM + z1];
        __syncwarp();

#define BWD_STEP(t, VR, VW, E0, E1)                                            \
    {                                                                          \
        int xp = x_sh[((t) >= 2) ? (t) - 2 : 0] * Z_DIM;                       \
        float d0, d1; DOT2(VR, d0, d1);                                        \
        float* bp = bw + (size_t)(t) * B_DIM * Z_DIM;                          \
        bp[z0] = d0; bp[z1] = d1;                                              \
        (VW)[z0] = (E0) * d0; (VW)[z1] = (E1) * d1;                            \
        E0 = emit[xp + z0]; E1 = emit[xp + z1];                                \
        __syncwarp();                                                          \
    }

        for (int t = S_LEN - 2; t >= 2; t -= 2) {
            BWD_STEP(t,     v_sh[1], v_sh[0], ee0, ee1);
            BWD_STEP(t - 1, v_sh[0], v_sh[1], eo0, eo1);
        }
        // t = 0: only beta needed
        {
            float d0, d1; DOT2(v_sh[1], d0, d1);
            bw[z0] = d0; bw[z1] = d1;
        }
#undef BWD_STEP
    }
#undef DOT2
}

// ---------------------------------------------------------------------------
// Posterior: post = alpha*beta / sum_z(alpha*beta). Streaming, HBM-bound.
// ---------------------------------------------------------------------------
__global__ __launch_bounds__(256)
void hmm_post_kernel(const float* __restrict__ alpha,
                     const float* __restrict__ beta,
                     float* __restrict__ post)
{
    const int gid = blockIdx.x * blockDim.x + threadIdx.x;
    const int row = gid >> 4;
    const int sub = gid & 15;

    const size_t off = (size_t)row * Z_DIM + sub * 4;
    float4 av = *reinterpret_cast<const float4*>(alpha + off);
    float4 bv = *reinterpret_cast<const float4*>(beta  + off);

    float4 ab;
    ab.x = av.x * bv.x; ab.y = av.y * bv.y;
    ab.z = av.z * bv.z; ab.w = av.w * bv.w;

    float s = (ab.x + ab.y) + (ab.z + ab.w);
    #pragma unroll
    for (int o = 8; o > 0; o >>= 1) s += __shfl_xor_sync(0xffffffffu, s, o);

    float inv = 1.0f / s;
    float4 p;
    p.x = ab.x * inv; p.y = ab.y * inv; p.z = ab.z * inv; p.w = ab.w * inv;
    *reinterpret_cast<float4*>(post + off) = p;
}

extern "C" void kernel_launch(void* const* d_in, const int* in_sizes, int n_in,
                              void* d_out, int out_size)
{
    const int*   inp  = (const int*)  d_in[0];   // [512, 256] int32
    const float* T    = (const float*)d_in[1];   // [64, 64]
    const float* pi   = (const float*)d_in[2];   // [64]
    const float* emit = (const float*)d_in[3];   // [10000, 64]

    float* out   = (float*)d_out;
    const size_t N = (size_t)S_LEN * B_DIM * Z_DIM;
    float* alpha = out;
    float* beta  = out + N;
    float* post  = out + 2 * N;

    hmm_fb_kernel<<<2 * B_DIM, 32>>>(inp, T, pi, emit, alpha, beta);

    const int rows = S_LEN * B_DIM;             // 131072
    const int threads = 256;
    const int blocks = rows * 16 / threads;     // 8192
    hmm_post_kernel<<<blocks, threads>>>(alpha, beta, post);
}

// round 8
// speedup vs baseline: 1.0324x; 1.0324x over previous
#include <cuda_runtime.h>
#include <cuda_bf16.h>

#define S_LEN 512
#define B_DIM 256
#define Z_DIM 64

// ---- packed f32x2 helpers (full fp32 precision) ----
__device__ __forceinline__ unsigned long long pack2(float lo, float hi) {
    unsigned long long r;
    asm("mov.b64 %0, {%1, %2};" : "=l"(r) : "f"(lo), "f"(hi));
    return r;
}
__device__ __forceinline__ unsigned long long fma2(unsigned long long a,
                                                   unsigned long long b,
                                                   unsigned long long c) {
    unsigned long long d;
    asm("fma.rn.f32x2 %0, %1, %2, %3;" : "=l"(d) : "l"(a), "l"(b), "l"(c));
    return d;
}
__device__ __forceinline__ unsigned long long add2(unsigned long long a,
                                                   unsigned long long b) {
    unsigned long long d;
    asm("add.rn.f32x2 %0, %1, %2;" : "=l"(d) : "l"(a), "l"(b));
    return d;
}
__device__ __forceinline__ float hsum2(unsigned long long v) {
    float lo, hi;
    asm("mov.b64 {%0, %1}, %2;" : "=f"(lo), "=f"(hi) : "l"(v));
    return lo + hi;
}

// ---------------------------------------------------------------------------
// One CTA (128 threads, 4 warps) per (batch, direction) chain.
//   tid: s = tid>>1 (state 0..63), h = tid&1 (K-half: k in [32h, 32h+32)).
//   Lane pair (2m, 2m+1) owns one state: shfl_xor(1) combines the two K-half
//   partials — no cross-warp traffic for the reduction.
//   Even lane -> STS recurrent vector; odd lane -> STG output row.
//   blocks [0,256):   forward  (T row s);  blocks [256,512): backward (T col s)
// Double-buffered smem vector, one __syncthreads per step, 2x time-unroll so
// all buffer / prefetch names are static (no local memory).
// ---------------------------------------------------------------------------
__global__ __launch_bounds__(128)
void hmm_fb_kernel(const int* __restrict__ inp,      // [S, B]
                   const float* __restrict__ T,      // [Z, Z]
                   const float* __restrict__ pi,     // [Z]
                   const float* __restrict__ emit,   // [X, Z]
                   float* __restrict__ alpha,        // [S, B, Z]
                   float* __restrict__ beta)         // [S, B, Z]
{
    const bool bwd = blockIdx.x >= B_DIM;
    const int  b   = blockIdx.x & (B_DIM - 1);
    const int  tid = threadIdx.x;
    const int  s   = tid >> 1;          // state
    const int  h   = tid & 1;           // K-half

    __shared__ __align__(16) float v_sh[2][Z_DIM];
    __shared__ int x_sh[S_LEN];

    #pragma unroll
    for (int t = tid; t < S_LEN; t += 128) x_sh[t] = inp[t * B_DIM + b];

    // This thread's 32 T-coefficients (16 packed pairs) for (state s, half h).
    unsigned long long Tp[16];
    if (!bwd) {
        const float* Trow = &T[s * Z_DIM + 32 * h];
        #pragma unroll
        for (int k = 0; k < 32; k += 4) {
            float4 v = *reinterpret_cast<const float4*>(Trow + k);
            Tp[k / 2]     = pack2(v.x, v.y);
            Tp[k / 2 + 1] = pack2(v.z, v.w);
        }
    } else {
        #pragma unroll
        for (int k = 0; k < 32; k += 2) {
            Tp[k / 2] = pack2(T[(32 * h + k)     * Z_DIM + s],
                              T[(32 * h + k + 1) * Z_DIM + s]);
        }
    }

    __syncthreads();   // x_sh fill visible to all threads (R7 crash fix)

    // Half-dot over this thread's 32 entries, then lane-pair combine.
#define DOTV(VR, vout)                                                         \
    {                                                                          \
        const ulonglong2* p2 =                                                 \
            reinterpret_cast<const ulonglong2*>(VR) + 8 * h;                   \
        unsigned long long s0 = 0, s1 = 0, s2 = 0, s3 = 0;                     \
        _Pragma("unroll")                                                      \
        for (int q = 0; q < 8; q++) {                                          \
            ulonglong2 u = p2[q];                                              \
            if ((q & 1) == 0) {                                                \
                s0 = fma2(u.x, Tp[2 * q],     s0);                             \
                s1 = fma2(u.y, Tp[2 * q + 1], s1);                             \
            } else {                                                           \
                s2 = fma2(u.x, Tp[2 * q],     s2);                             \
                s3 = fma2(u.y, Tp[2 * q + 1], s3);                             \
            }                                                                  \
        }                                                                      \
        float p = hsum2(add2(add2(s0, s2), add2(s1, s3)));                     \
        vout = p + __shfl_xor_sync(0xffffffffu, p, 1);                         \
    }

    if (!bwd) {
        float* aw = alpha + (size_t)b * Z_DIM;
        // t = 0
        float a0 = emit[x_sh[0] * Z_DIM + s] * pi[s];
        if (h == 0) v_sh[0][s] = a0; else aw[s] = a0;
        float eo = emit[x_sh[1] * Z_DIM + s];   // e for odd steps
        float ee = emit[x_sh[2] * Z_DIM + s];   // e for even steps
        __syncthreads();

#define FWD_STEP(t, VR, VW, E)                                                 \
    {                                                                          \
        int xp = x_sh[((t) + 2 < S_LEN) ? (t) + 2 : S_LEN - 1] * Z_DIM;        \
        float v; DOTV(VR, v);                                                  \
        float n = (E) * v;                                                     \
        E = emit[xp + s];                                                      \
        if (h == 0) (VW)[s] = n;                                               \
        else        aw[(size_t)(t) * B_DIM * Z_DIM + s] = n;                   \
        __syncthreads();                                                       \
    }

        for (int t = 1; t < S_LEN - 1; t += 2) {
            FWD_STEP(t,     v_sh[0], v_sh[1], eo);
            FWD_STEP(t + 1, v_sh[1], v_sh[0], ee);
        }
        FWD_STEP(S_LEN - 1, v_sh[0], v_sh[1], eo);
#undef FWD_STEP
    } else {
        float* bw = beta + (size_t)b * Z_DIM;
        // t = S-1: beta = 1, c[S-1] = e[S-1]
        {
            float c = emit[x_sh[S_LEN - 1] * Z_DIM + s];
            if (h == 0) v_sh[1][s] = c;
            else        bw[(size_t)(S_LEN - 1) * B_DIM * Z_DIM + s] = 1.0f;
        }
        float ee = emit[x_sh[S_LEN - 2] * Z_DIM + s];   // e for even steps
        float eo = emit[x_sh[S_LEN - 3] * Z_DIM + s];   // e for odd steps
        __syncthreads();

#define BWD_STEP(t, VR, VW, E)                                                 \
    {                                                                          \
        int xp = x_sh[((t) >= 2) ? (t) - 2 : 0] * Z_DIM;                       \
        float v; DOTV(VR, v);                                                  \
        float c = (E) * v;                                                     \
        E = emit[xp + s];                                                      \
        if (h == 0) (VW)[s] = c;                                               \
        else        bw[(size_t)(t) * B_DIM * Z_DIM + s] = v;                   \
        __syncthreads();                                                       \
    }

        for (int t = S_LEN - 2; t >= 2; t -= 2) {
            BWD_STEP(t,     v_sh[1], v_sh[0], ee);
            BWD_STEP(t - 1, v_sh[0], v_sh[1], eo);
        }
        // t = 0: only beta needed
        {
            float v; DOTV(v_sh[1], v);
            if (h == 1) bw[s] = v;
        }
#undef BWD_STEP
    }
#undef DOTV
}

// ---------------------------------------------------------------------------
// Posterior: post = alpha*beta / sum_z(alpha*beta). Streaming, HBM-bound.
// ---------------------------------------------------------------------------
__global__ __launch_bounds__(256)
void hmm_post_kernel(const float* __restrict__ alpha,
                     const float* __restrict__ beta,
                     float* __restrict__ post)
{
    const int gid = blockIdx.x * blockDim.x + threadIdx.x;
    const int row = gid >> 4;
    const int sub = gid & 15;

    const size_t off = (size_t)row * Z_DIM + sub * 4;
    float4 av = *reinterpret_cast<const float4*>(alpha + off);
    float4 bv = *reinterpret_cast<const float4*>(beta  + off);

    float4 ab;
    ab.x = av.x * bv.x; ab.y = av.y * bv.y;
    ab.z = av.z * bv.z; ab.w = av.w * bv.w;

    float s = (ab.x + ab.y) + (ab.z + ab.w);
    #pragma unroll
    for (int o = 8; o > 0; o >>= 1) s += __shfl_xor_sync(0xffffffffu, s, o);

    float inv = 1.0f / s;
    float4 p;
    p.x = ab.x * inv; p.y = ab.y * inv; p.z = ab.z * inv; p.w = ab.w * inv;
    *reinterpret_cast<float4*>(post + off) = p;
}

extern "C" void kernel_launch(void* const* d_in, const int* in_sizes, int n_in,
                              void* d_out, int out_size)
{
    const int*   inp  = (const int*)  d_in[0];   // [512, 256] int32
    const float* T    = (const float*)d_in[1];   // [64, 64]
    const float* pi   = (const float*)d_in[2];   // [64]
    const float* emit = (const float*)d_in[3];   // [10000, 64]

    float* out   = (float*)d_out;
    const size_t N = (size_t)S_LEN * B_DIM * Z_DIM;
    float* alpha = out;
    float* beta  = out + N;
    float* post  = out + 2 * N;

    hmm_fb_kernel<<<2 * B_DIM, 128>>>(inp, T, pi, emit, alpha, beta);

    const int rows = S_LEN * B_DIM;             // 131072
    const int threads = 256;
    const int blocks = rows * 16 / threads;     // 8192
    hmm_post_kernel<<<blocks, threads>>>(alpha, beta, post);
}